// round 15
// baseline (speedup 1.0000x reference)
#include <cuda_runtime.h>
#include <cuda_bf16.h>
#include <math.h>
#include <cstdint>

#define BS_    2
#define NQ_    4096
#define DIM_   768
#define HEADS_ 6
#define POINTS_ 4
#define HD_    128
#define HW_    64
#define NROWS_ (BS_*NQ_)   // 8192
#define NCAT   128

// ---------------- scratch ----------------
__device__ __align__(128) __nv_bfloat16 g_qnb  [NROWS_*DIM_];
__device__ __align__(128) __nv_bfloat16 g_featb[NROWS_*DIM_];
__device__ __align__(128) __nv_bfloat16 g_valb [NROWS_*DIM_];
__device__ __align__(128) __nv_bfloat16 g_attnb[NROWS_*DIM_];
__device__ __align__(128) __nv_bfloat16 g_vpwt [DIM_*DIM_];
__device__ __align__(128) __nv_bfloat16 g_outwt[DIM_*DIM_];
__device__ __align__(128) __nv_bfloat16 g_catwt[NCAT*DIM_];
__device__ __align__(128) float g_bcat[NCAT];
__device__ __align__(128) float g_logits[NROWS_*NCAT];

// ================= PTX helpers =================
__device__ __forceinline__ uint32_t smem_u32(const void* p) {
    uint32_t a;
    asm("{ .reg .u64 t; cvta.to.shared.u64 t, %1; cvt.u32.u64 %0, t; }" : "=r"(a) : "l"(p));
    return a;
}
__device__ __forceinline__ void cp16(uint32_t dst, const void* src) {
    asm volatile("cp.async.cg.shared.global [%0], [%1], 16;" :: "r"(dst), "l"(src));
}
#define CP_COMMIT() asm volatile("cp.async.commit_group;" ::: "memory")

__device__ __forceinline__ void ldsm4(uint32_t* r, uint32_t addr) {
    asm volatile("ldmatrix.sync.aligned.m8n8.x4.shared.b16 {%0,%1,%2,%3}, [%4];"
                 : "=r"(r[0]), "=r"(r[1]), "=r"(r[2]), "=r"(r[3]) : "r"(addr));
}
__device__ __forceinline__ void mma_bf16(float* c, const uint32_t* a, const uint32_t* b) {
    asm volatile("mma.sync.aligned.m16n8k16.row.col.f32.bf16.bf16.f32 "
                 "{%0,%1,%2,%3}, {%4,%5,%6,%7}, {%8,%9}, {%0,%1,%2,%3};"
                 : "+f"(c[0]), "+f"(c[1]), "+f"(c[2]), "+f"(c[3])
                 : "r"(a[0]), "r"(a[1]), "r"(a[2]), "r"(a[3]), "r"(b[0]), "r"(b[1]));
}

// ---------------- fused prologue: ln | convA | convT x2 | convW ----------------
#define PB_LN   (NROWS_/8)                   // 1024
#define PB_CA   (NROWS_*DIM_/4/768)          // 2048
#define PB_CT   ((DIM_/32)*(DIM_/32)*2)      // 1152
#define PB_CW   ((NCAT*DIM_)/384)            // 256
#define PB_TOT  (PB_LN + PB_CA + PB_CT + PB_CW)

__global__ __launch_bounds__(384) void prologue_kernel(
    const float* __restrict__ query,
    const float* __restrict__ lnw, const float* __restrict__ lnb,
    const float* __restrict__ feat,
    const float* __restrict__ vpw, const float* __restrict__ outw,
    const float* __restrict__ offw, const float* __restrict__ offb,
    const float* __restrict__ aww,  const float* __restrict__ awb)
{
    __shared__ __align__(16) float sh[32 * 33];
    int bid = blockIdx.x;
    int tid = threadIdx.x;

    if (bid < PB_LN) {
        int warp = tid >> 5, lane = tid & 31;
        if (warp < 8) {
            int row = bid * 8 + warp;
            const float4* x4 = (const float4*)(query + (size_t)row * DIM_);
            float4 v[6];
            float s = 0.f;
            #pragma unroll
            for (int j = 0; j < 6; j++) {
                v[j] = x4[lane + j * 32];
                s += v[j].x + v[j].y + v[j].z + v[j].w;
            }
            #pragma unroll
            for (int o = 16; o; o >>= 1) s += __shfl_xor_sync(0xffffffffu, s, o);
            float mean = s * (1.f / DIM_);
            float var = 0.f;
            #pragma unroll
            for (int j = 0; j < 6; j++) {
                float d0 = v[j].x - mean, d1 = v[j].y - mean;
                float d2 = v[j].z - mean, d3 = v[j].w - mean;
                var += d0 * d0 + d1 * d1 + d2 * d2 + d3 * d3;
            }
            #pragma unroll
            for (int o = 16; o; o >>= 1) var += __shfl_xor_sync(0xffffffffu, var, o);
            float rstd = rsqrtf(var * (1.f / DIM_) + 1e-6f);
            const float4* w4 = (const float4*)lnw;
            const float4* b4 = (const float4*)lnb;
            uint2* o2 = (uint2*)(g_qnb + (size_t)row * DIM_);
            #pragma unroll
            for (int j = 0; j < 6; j++) {
                float4 ww = w4[lane + j * 32];
                float4 bb = b4[lane + j * 32];
                float f0 = (v[j].x - mean) * rstd * ww.x + bb.x;
                float f1 = (v[j].y - mean) * rstd * ww.y + bb.y;
                float f2 = (v[j].z - mean) * rstd * ww.z + bb.z;
                float f3 = (v[j].w - mean) * rstd * ww.w + bb.w;
                uint2 pk;
                asm("cvt.rn.bf16x2.f32 %0, %1, %2;" : "=r"(pk.x) : "f"(f1), "f"(f0));
                asm("cvt.rn.bf16x2.f32 %0, %1, %2;" : "=r"(pk.y) : "f"(f3), "f"(f2));
                o2[lane + j * 32] = pk;
            }
        }
    } else if (bid < PB_LN + PB_CA) {
        int base = (bid - PB_LN) * 768 + tid;
        #pragma unroll
        for (int u = 0; u < 2; u++) {
            int i = base + u * 384;
            float4 v = ((const float4*)feat)[i];
            uint32_t lo, hi;
            asm("cvt.rn.bf16x2.f32 %0, %1, %2;" : "=r"(lo) : "f"(v.y), "f"(v.x));
            asm("cvt.rn.bf16x2.f32 %0, %1, %2;" : "=r"(hi) : "f"(v.w), "f"(v.z));
            ((uint2*)g_featb)[i] = make_uint2(lo, hi);
        }
    } else if (bid < PB_LN + PB_CA + PB_CT) {
        int t = bid - (PB_LN + PB_CA);
        int z = t / 576;
        int rem = t % 576;
        const float* W    = z ? outw : vpw;
        __nv_bfloat16* Wt = z ? g_outwt : g_vpwt;
        int bx = (rem % 24) * 32, by = (rem / 24) * 32;
        int tx = tid & 31, ty = (tid >> 5);
        if (ty < 8) {
            #pragma unroll
            for (int i = 0; i < 32; i += 8)
                sh[(ty + i) * 33 + tx] = W[(size_t)(by + ty + i) * DIM_ + bx + tx];
        }
        __syncthreads();
        if (ty < 8) {
            #pragma unroll
            for (int i = 0; i < 32; i += 8)
                Wt[(size_t)(bx + ty + i) * DIM_ + by + tx] =
                    __float2bfloat16(sh[tx * 33 + ty + i]);
        }
    } else {
        int lb = bid - (PB_LN + PB_CA + PB_CT);
        int i = lb * 384 + tid;
        int c = i / DIM_, k = i % DIM_;
        float v = 0.f;
        if (c < 48)      v = offw[(size_t)k * 48 + c];
        else if (c < 72) v = aww[(size_t)k * 24 + (c - 48)];
        g_catwt[i] = __float2bfloat16(v);
        if (lb == 0 && tid < NCAT)
            g_bcat[tid] = (tid < 48) ? offb[tid] : (tid < 72 ? awb[tid - 48] : 0.f);
    }
}

// ------- HMMA bf16 GEMM: CTA 128x64, 4 warps 64x32, KC=64, 3 stages ----------------
// MODE 0: C = bf16(acc + bias)
// MODE 1: C = fp32(resid + gamma*(acc + bias))
// MODE 2: C = fp32(acc + bias)
#define KC       64
#define RSB      144
#define A_BYTES  (128 * RSB)          // 18432
#define B_BYTES  (64 * RSB)           // 9216
#define STAGE_B  (A_BYTES + B_BYTES)  // 27648
#define NSTEP    (DIM_ / KC)          // 12
#define NVT      (DIM_ / 64)          // 12 value n-tiles

template <int MODE>
__global__ __launch_bounds__(128, 2) void gemm_bf16(
    const __nv_bfloat16* __restrict__ A, const __nv_bfloat16* __restrict__ Bt,
    const float* __restrict__ bias, void* __restrict__ Cout, int ldc,
    const float* __restrict__ resid, const float* __restrict__ gamma)
{
    extern __shared__ __align__(128) char dsm[];
    uint32_t sb = smem_u32(dsm);
    int tid = threadIdx.x, wid = tid >> 5, lane = tid & 31;
    int m0 = blockIdx.y * 128;
    int n0 = blockIdx.x * 64;
    int wm = (wid & 1) * 64;
    int wn = (wid >> 1) * 32;

    int ar[8], ac[8];
    #pragma unroll
    for (int j = 0; j < 8; j++) {
        int id = j * 128 + tid;
        ar[j] = id >> 3;
        ac[j] = (id & 7) * 8;
    }
    int br[4], bc[4];
    #pragma unroll
    for (int j = 0; j < 4; j++) {
        int id = j * 128 + tid;
        br[j] = id >> 3;
        bc[j] = (id & 7) * 8;
    }

    auto load_stage = [&](int s) {
        uint32_t base = sb + (s % 3) * STAGE_B;
        int k0 = s * KC;
        #pragma unroll
        for (int j = 0; j < 8; j++)
            cp16(base + ar[j] * RSB + ac[j] * 2,
                 A + (size_t)(m0 + ar[j]) * DIM_ + k0 + ac[j]);
        #pragma unroll
        for (int j = 0; j < 4; j++)
            cp16(base + A_BYTES + br[j] * RSB + bc[j] * 2,
                 Bt + (size_t)(n0 + br[j]) * DIM_ + k0 + bc[j]);
        CP_COMMIT();
    };

    int a_r  = wm + (lane & 15);
    int a_k  = (lane >> 4) * 8;
    int b_n  = wn + (lane & 7) + ((lane >> 4) << 3);
    int b_k  = ((lane >> 3) & 1) * 8;

    float acc[4][4][4] = {};
    uint32_t af[2][4][4], bf[2][2][4];

    auto load_frags = [&](uint32_t abase, uint32_t bbase, int kk, int buf) {
        #pragma unroll
        for (int mt = 0; mt < 4; mt++)
            ldsm4(af[buf][mt], abase + (a_r + mt * 16) * RSB + (kk * 16 + a_k) * 2);
        #pragma unroll
        for (int np = 0; np < 2; np++)
            ldsm4(bf[buf][np], bbase + (b_n + np * 16) * RSB + (kk * 16 + b_k) * 2);
    };
    auto do_mma = [&](int buf) {
        #pragma unroll
        for (int mt = 0; mt < 4; mt++)
            #pragma unroll
            for (int nt = 0; nt < 4; nt++)
                mma_bf16(acc[mt][nt], af[buf][mt], &bf[buf][nt >> 1][(nt & 1) * 2]);
    };

    load_stage(0); load_stage(1);

    for (int s = 0; s < NSTEP; s++) {
        if (s + 2 < NSTEP) {
            asm volatile("cp.async.wait_group 1;" ::: "memory");
            __syncthreads();
            load_stage(s + 2);
        } else if (s + 1 < NSTEP) {
            asm volatile("cp.async.wait_group 1;" ::: "memory");
            __syncthreads();
        } else {
            asm volatile("cp.async.wait_group 0;" ::: "memory");
            __syncthreads();
        }

        uint32_t abase = sb + (s % 3) * STAGE_B;
        uint32_t bbase = abase + A_BYTES;

        load_frags(abase, bbase, 0, 0);
        #pragma unroll
        for (int kk = 0; kk < 4; kk++) {
            if (kk < 3) load_frags(abase, bbase, kk + 1, (kk + 1) & 1);
            do_mma(kk & 1);
        }
    }

    int crow0 = m0 + wm + (lane >> 2);
    int ccol0 = n0 + wn + (lane & 3) * 2;
    #pragma unroll
    for (int mt = 0; mt < 4; mt++) {
        #pragma unroll
        for (int half = 0; half < 2; half++) {
            int row = crow0 + mt * 16 + half * 8;
            #pragma unroll
            for (int nt = 0; nt < 4; nt++) {
                int col = ccol0 + nt * 8;
                float f0 = acc[mt][nt][half * 2]     + bias[col];
                float f1 = acc[mt][nt][half * 2 + 1] + bias[col + 1];
                if (MODE == 0) {
                    uint32_t pk;
                    asm("cvt.rn.bf16x2.f32 %0, %1, %2;" : "=r"(pk) : "f"(f1), "f"(f0));
                    *(uint32_t*)((__nv_bfloat16*)Cout + (size_t)row * ldc + col) = pk;
                } else if (MODE == 1) {
                    const float* qr = resid + (size_t)row * ldc + col;
                    float2 o;
                    o.x = qr[0] + gamma[col]     * f0;
                    o.y = qr[1] + gamma[col + 1] * f1;
                    *(float2*)((float*)Cout + (size_t)row * ldc + col) = o;
                } else {
                    float2 o; o.x = f0; o.y = f1;
                    *(float2*)((float*)Cout + (size_t)row * ldc + col) = o;
                }
            }
        }
    }
}

// ---------------- bilinear sampling (round-12 proven version) ----------------
__global__ __launch_bounds__(256) void sample_kernel(const float* __restrict__ refp)
{
    int w = blockIdx.x * 8 + (threadIdx.x >> 5);
    int lane = threadIdx.x & 31;
    int h  = w % HEADS_;
    int qi = w / HEADS_;
    int b  = qi >> 12;

    const float* lg = g_logits + (size_t)qi * NCAT;
    float x = (lane < 24) ? lg[48 + lane] : -1e30f;
    float m = x;
    #pragma unroll
    for (int o = 16; o; o >>= 1) m = fmaxf(m, __shfl_xor_sync(0xffffffffu, m, o));
    float e = (lane < 24) ? __expf(x - m) : 0.f;
    float ss = e;
    #pragma unroll
    for (int o = 16; o; o >>= 1) ss += __shfl_xor_sync(0xffffffffu, ss, o);
    float p_all = e / ss;
    float off = (lane < 8) ? lg[h * 8 + lane] : 0.f;
    float rx = refp[(size_t)qi * 2 + 0] * (float)HW_ - 0.5f;
    float ry = refp[(size_t)qi * 2 + 1] * (float)HW_ - 0.5f;

    float a0 = 0.f, a1 = 0.f, a2 = 0.f, a3 = 0.f;
    const uint2* vp = (const uint2*)(g_valb + (size_t)b * NQ_ * DIM_ + h * HD_) + lane;
    const int POS = DIM_ / 4;

    #pragma unroll
    for (int p = 0; p < POINTS_; p++) {
        float aw = __shfl_sync(0xffffffffu, p_all, h * POINTS_ + p);
        float xf = rx + __shfl_sync(0xffffffffu, off, p * 2);
        float yf = ry + __shfl_sync(0xffffffffu, off, p * 2 + 1);
        float x0f = floorf(xf), y0f = floorf(yf);
        float wx = xf - x0f, wy = yf - y0f;
        int x0 = (int)x0f, y0 = (int)y0f;
        #pragma unroll
        for (int dy = 0; dy < 2; dy++) {
            #pragma unroll
            for (int dx = 0; dx < 2; dx++) {
                int xi = x0 + dx, yi = y0 + dy;
                bool v = (xi >= 0) & (xi < HW_) & (yi >= 0) & (yi < HW_);
                int xc = min(max(xi, 0), HW_ - 1);
                int yc = min(max(yi, 0), HW_ - 1);
                float cw = aw * (dy ? wy : 1.f - wy) * (dx ? wx : 1.f - wx);
                cw = v ? cw : 0.f;
                uint2 q = vp[(yc * HW_ + xc) * POS];
                float2 f0 = __bfloat1622float2(*(__nv_bfloat162*)&q.x);
                float2 f1 = __bfloat1622float2(*(__nv_bfloat162*)&q.y);
                a0 = fmaf(cw, f0.x, a0);
                a1 = fmaf(cw, f0.y, a1);
                a2 = fmaf(cw, f1.x, a2);
                a3 = fmaf(cw, f1.y, a3);
            }
        }
    }
    uint2 pk;
    asm("cvt.rn.bf16x2.f32 %0, %1, %2;" : "=r"(pk.x) : "f"(a1), "f"(a0));
    asm("cvt.rn.bf16x2.f32 %0, %1, %2;" : "=r"(pk.y) : "f"(a3), "f"(a2));
    ((uint2*)(g_attnb + (size_t)qi * DIM_ + h * HD_))[lane] = pk;
}

// ---------------- launch ----------------
extern "C" void kernel_launch(void* const* d_in, const int* in_sizes, int n_in,
                              void* d_out, int out_size)
{
    const float* query = (const float*)d_in[0];
    const float* refp  = (const float*)d_in[1];
    const float* feat  = (const float*)d_in[2];
    const float* lnw   = (const float*)d_in[5];
    const float* lnb   = (const float*)d_in[6];
    const float* vpw   = (const float*)d_in[7];
    const float* vpb   = (const float*)d_in[8];
    const float* offw  = (const float*)d_in[9];
    const float* offb  = (const float*)d_in[10];
    const float* aww   = (const float*)d_in[11];
    const float* awb   = (const float*)d_in[12];
    const float* outw  = (const float*)d_in[13];
    const float* outb  = (const float*)d_in[14];
    const float* gamma = (const float*)d_in[15];
    float* out = (float*)d_out;

    __nv_bfloat16 *p_featb, *p_valb, *p_attnb, *p_vpwt, *p_outwt, *p_catwt, *p_qnb;
    float *p_bcat, *p_logits;
    cudaGetSymbolAddress((void**)&p_featb, g_featb);
    cudaGetSymbolAddress((void**)&p_valb,  g_valb);
    cudaGetSymbolAddress((void**)&p_attnb, g_attnb);
    cudaGetSymbolAddress((void**)&p_vpwt,  g_vpwt);
    cudaGetSymbolAddress((void**)&p_outwt, g_outwt);
    cudaGetSymbolAddress((void**)&p_catwt, g_catwt);
    cudaGetSymbolAddress((void**)&p_qnb,   g_qnb);
    cudaGetSymbolAddress((void**)&p_bcat,  g_bcat);
    cudaGetSymbolAddress((void**)&p_logits,g_logits);

    const int SMEM = 3 * STAGE_B;   // 82944
    cudaFuncSetAttribute(gemm_bf16<0>, cudaFuncAttributeMaxDynamicSharedMemorySize, SMEM);
    cudaFuncSetAttribute(gemm_bf16<1>, cudaFuncAttributeMaxDynamicSharedMemorySize, SMEM);
    cudaFuncSetAttribute(gemm_bf16<2>, cudaFuncAttributeMaxDynamicSharedMemorySize, SMEM);

    // second stream + events for the concurrent logits GEMM (graph-capturable fork/join)
    cudaStream_t s2;
    cudaStreamCreateWithFlags(&s2, cudaStreamNonBlocking);
    cudaEvent_t eFork, eJoin;
    cudaEventCreateWithFlags(&eFork, cudaEventDisableTiming);
    cudaEventCreateWithFlags(&eJoin, cudaEventDisableTiming);

    dim3 g0(NVT, NROWS_ / 128);       // (12, 64) value GEMM only
    dim3 gl(NCAT / 64, NROWS_ / 128); // (2, 64)  logits GEMM
    dim3 g1(NVT, NROWS_ / 128);       // (12, 64)

    prologue_kernel<<<PB_TOT, 384>>>(query, lnw, lnb, feat, vpw, outw,
                                     offw, offb, aww, awb);
    cudaEventRecord(eFork, 0);
    cudaStreamWaitEvent(s2, eFork, 0);
    gemm_bf16<0><<<g0, 128, SMEM>>>(p_featb, p_vpwt, vpb, p_valb, DIM_, nullptr, nullptr);
    gemm_bf16<2><<<gl, 128, SMEM, s2>>>(p_qnb, p_catwt, p_bcat, p_logits, NCAT, nullptr, nullptr);
    cudaEventRecord(eJoin, s2);
    cudaStreamWaitEvent(0, eJoin, 0);
    sample_kernel<<<NROWS_ * HEADS_ / 8, 256>>>(refp);
    gemm_bf16<1><<<g1, 128, SMEM>>>(p_attnb, p_outwt, outb, out, DIM_, query, gamma);
}

// round 16
// speedup vs baseline: 1.0651x; 1.0651x over previous
#include <cuda_runtime.h>
#include <cuda_bf16.h>
#include <math.h>
#include <cstdint>

#define BS_    2
#define NQ_    4096
#define DIM_   768
#define HEADS_ 6
#define POINTS_ 4
#define HD_    128
#define HW_    64
#define NROWS_ (BS_*NQ_)   // 8192
#define NCAT   128

// ---------------- scratch ----------------
__device__ __align__(128) __nv_bfloat16 g_qnb  [NROWS_*DIM_];
__device__ __align__(128) __nv_bfloat16 g_featb[NROWS_*DIM_];
__device__ __align__(128) __nv_bfloat16 g_valb [NROWS_*DIM_];
__device__ __align__(128) __nv_bfloat16 g_attnb[NROWS_*DIM_];
__device__ __align__(128) __nv_bfloat16 g_vpwt [DIM_*DIM_];
__device__ __align__(128) __nv_bfloat16 g_outwt[DIM_*DIM_];
__device__ __align__(128) __nv_bfloat16 g_catwt[NCAT*DIM_];
__device__ __align__(128) float g_bcat[NCAT];
__device__ __align__(128) float g_logits[NROWS_*NCAT];
__device__ __align__(128) float4 g_wdesc[NROWS_*24];   // per-point 4 corner weights
__device__ __align__(128) uint2  g_pdesc[NROWS_*24];   // per-point 4 packed u16 indices

// ================= PTX helpers =================
__device__ __forceinline__ uint32_t smem_u32(const void* p) {
    uint32_t a;
    asm("{ .reg .u64 t; cvta.to.shared.u64 t, %1; cvt.u32.u64 %0, t; }" : "=r"(a) : "l"(p));
    return a;
}
__device__ __forceinline__ void cp16(uint32_t dst, const void* src) {
    asm volatile("cp.async.cg.shared.global [%0], [%1], 16;" :: "r"(dst), "l"(src));
}
#define CP_COMMIT() asm volatile("cp.async.commit_group;" ::: "memory")

__device__ __forceinline__ void ldsm4(uint32_t* r, uint32_t addr) {
    asm volatile("ldmatrix.sync.aligned.m8n8.x4.shared.b16 {%0,%1,%2,%3}, [%4];"
                 : "=r"(r[0]), "=r"(r[1]), "=r"(r[2]), "=r"(r[3]) : "r"(addr));
}
__device__ __forceinline__ void mma_bf16(float* c, const uint32_t* a, const uint32_t* b) {
    asm volatile("mma.sync.aligned.m16n8k16.row.col.f32.bf16.bf16.f32 "
                 "{%0,%1,%2,%3}, {%4,%5,%6,%7}, {%8,%9}, {%0,%1,%2,%3};"
                 : "+f"(c[0]), "+f"(c[1]), "+f"(c[2]), "+f"(c[3])
                 : "r"(a[0]), "r"(a[1]), "r"(a[2]), "r"(a[3]), "r"(b[0]), "r"(b[1]));
}

// ---------------- fused prologue: ln | convA | convT x2 | convW ----------------
#define PB_LN   (NROWS_/8)                   // 1024
#define PB_CA   (NROWS_*DIM_/4/768)          // 2048
#define PB_CT   ((DIM_/32)*(DIM_/32)*2)      // 1152
#define PB_CW   ((NCAT*DIM_)/384)            // 256
#define PB_TOT  (PB_LN + PB_CA + PB_CT + PB_CW)

__global__ __launch_bounds__(384) void prologue_kernel(
    const float* __restrict__ query,
    const float* __restrict__ lnw, const float* __restrict__ lnb,
    const float* __restrict__ feat,
    const float* __restrict__ vpw, const float* __restrict__ outw,
    const float* __restrict__ offw, const float* __restrict__ offb,
    const float* __restrict__ aww,  const float* __restrict__ awb)
{
    __shared__ __align__(16) float sh[32 * 33];
    int bid = blockIdx.x;
    int tid = threadIdx.x;

    if (bid < PB_LN) {
        int warp = tid >> 5, lane = tid & 31;
        if (warp < 8) {
            int row = bid * 8 + warp;
            const float4* x4 = (const float4*)(query + (size_t)row * DIM_);
            float4 v[6];
            float s = 0.f;
            #pragma unroll
            for (int j = 0; j < 6; j++) {
                v[j] = x4[lane + j * 32];
                s += v[j].x + v[j].y + v[j].z + v[j].w;
            }
            #pragma unroll
            for (int o = 16; o; o >>= 1) s += __shfl_xor_sync(0xffffffffu, s, o);
            float mean = s * (1.f / DIM_);
            float var = 0.f;
            #pragma unroll
            for (int j = 0; j < 6; j++) {
                float d0 = v[j].x - mean, d1 = v[j].y - mean;
                float d2 = v[j].z - mean, d3 = v[j].w - mean;
                var += d0 * d0 + d1 * d1 + d2 * d2 + d3 * d3;
            }
            #pragma unroll
            for (int o = 16; o; o >>= 1) var += __shfl_xor_sync(0xffffffffu, var, o);
            float rstd = rsqrtf(var * (1.f / DIM_) + 1e-6f);
            const float4* w4 = (const float4*)lnw;
            const float4* b4 = (const float4*)lnb;
            uint2* o2 = (uint2*)(g_qnb + (size_t)row * DIM_);
            #pragma unroll
            for (int j = 0; j < 6; j++) {
                float4 ww = w4[lane + j * 32];
                float4 bb = b4[lane + j * 32];
                float f0 = (v[j].x - mean) * rstd * ww.x + bb.x;
                float f1 = (v[j].y - mean) * rstd * ww.y + bb.y;
                float f2 = (v[j].z - mean) * rstd * ww.z + bb.z;
                float f3 = (v[j].w - mean) * rstd * ww.w + bb.w;
                uint2 pk;
                asm("cvt.rn.bf16x2.f32 %0, %1, %2;" : "=r"(pk.x) : "f"(f1), "f"(f0));
                asm("cvt.rn.bf16x2.f32 %0, %1, %2;" : "=r"(pk.y) : "f"(f3), "f"(f2));
                o2[lane + j * 32] = pk;
            }
        }
    } else if (bid < PB_LN + PB_CA) {
        int base = (bid - PB_LN) * 768 + tid;
        #pragma unroll
        for (int u = 0; u < 2; u++) {
            int i = base + u * 384;
            float4 v = ((const float4*)feat)[i];
            uint32_t lo, hi;
            asm("cvt.rn.bf16x2.f32 %0, %1, %2;" : "=r"(lo) : "f"(v.y), "f"(v.x));
            asm("cvt.rn.bf16x2.f32 %0, %1, %2;" : "=r"(hi) : "f"(v.w), "f"(v.z));
            ((uint2*)g_featb)[i] = make_uint2(lo, hi);
        }
    } else if (bid < PB_LN + PB_CA + PB_CT) {
        int t = bid - (PB_LN + PB_CA);
        int z = t / 576;
        int rem = t % 576;
        const float* W    = z ? outw : vpw;
        __nv_bfloat16* Wt = z ? g_outwt : g_vpwt;
        int bx = (rem % 24) * 32, by = (rem / 24) * 32;
        int tx = tid & 31, ty = (tid >> 5);
        if (ty < 8) {
            #pragma unroll
            for (int i = 0; i < 32; i += 8)
                sh[(ty + i) * 33 + tx] = W[(size_t)(by + ty + i) * DIM_ + bx + tx];
        }
        __syncthreads();
        if (ty < 8) {
            #pragma unroll
            for (int i = 0; i < 32; i += 8)
                Wt[(size_t)(bx + ty + i) * DIM_ + by + tx] =
                    __float2bfloat16(sh[tx * 33 + ty + i]);
        }
    } else {
        int lb = bid - (PB_LN + PB_CA + PB_CT);
        int i = lb * 384 + tid;
        int c = i / DIM_, k = i % DIM_;
        float v = 0.f;
        if (c < 48)      v = offw[(size_t)k * 48 + c];
        else if (c < 72) v = aww[(size_t)k * 24 + (c - 48)];
        g_catwt[i] = __float2bfloat16(v);
        if (lb == 0 && tid < NCAT)
            g_bcat[tid] = (tid < 48) ? offb[tid] : (tid < 72 ? awb[tid - 48] : 0.f);
    }
}

// ------- HMMA bf16 GEMM: CTA 128x64, 4 warps 64x32, KC=64, 3 stages (round-12) ----
#define KC       64
#define RSB      144
#define A_BYTES  (128 * RSB)          // 18432
#define B_BYTES  (64 * RSB)           // 9216
#define STAGE_B  (A_BYTES + B_BYTES)  // 27648
#define NSTEP    (DIM_ / KC)          // 12
#define NVT      (DIM_ / 64)          // 12 value n-tiles

template <int MODE>
__global__ __launch_bounds__(128, 2) void gemm_bf16(
    const __nv_bfloat16* __restrict__ A, const __nv_bfloat16* __restrict__ Bt,
    const float* __restrict__ bias, void* __restrict__ Cout, int ldc,
    const float* __restrict__ resid, const float* __restrict__ gamma)
{
    extern __shared__ __align__(128) char dsm[];
    uint32_t sb = smem_u32(dsm);
    int tid = threadIdx.x, wid = tid >> 5, lane = tid & 31;
    int m0 = blockIdx.y * 128;
    int wm = (wid & 1) * 64;
    int wn = (wid >> 1) * 32;

    bool lgt = (MODE == 0) && ((int)blockIdx.x >= NVT);
    const __nv_bfloat16* Ap  = lgt ? g_qnb   : A;
    const __nv_bfloat16* Bp  = lgt ? g_catwt : Bt;
    const float*         bp  = lgt ? g_bcat  : bias;
    int n0   = lgt ? ((int)blockIdx.x - NVT) * 64 : blockIdx.x * 64;
    int ldcc = lgt ? NCAT : ldc;

    int ar[8], ac[8];
    #pragma unroll
    for (int j = 0; j < 8; j++) {
        int id = j * 128 + tid;
        ar[j] = id >> 3;
        ac[j] = (id & 7) * 8;
    }
    int br[4], bc[4];
    #pragma unroll
    for (int j = 0; j < 4; j++) {
        int id = j * 128 + tid;
        br[j] = id >> 3;
        bc[j] = (id & 7) * 8;
    }

    auto load_stage = [&](int s) {
        uint32_t base = sb + (s % 3) * STAGE_B;
        int k0 = s * KC;
        #pragma unroll
        for (int j = 0; j < 8; j++)
            cp16(base + ar[j] * RSB + ac[j] * 2,
                 Ap + (size_t)(m0 + ar[j]) * DIM_ + k0 + ac[j]);
        #pragma unroll
        for (int j = 0; j < 4; j++)
            cp16(base + A_BYTES + br[j] * RSB + bc[j] * 2,
                 Bp + (size_t)(n0 + br[j]) * DIM_ + k0 + bc[j]);
        CP_COMMIT();
    };

    int a_r  = wm + (lane & 15);
    int a_k  = (lane >> 4) * 8;
    int b_n  = wn + (lane & 7) + ((lane >> 4) << 3);
    int b_k  = ((lane >> 3) & 1) * 8;

    float acc[4][4][4] = {};
    uint32_t af[2][4][4], bf[2][2][4];

    auto load_frags = [&](uint32_t abase, uint32_t bbase, int kk, int buf) {
        #pragma unroll
        for (int mt = 0; mt < 4; mt++)
            ldsm4(af[buf][mt], abase + (a_r + mt * 16) * RSB + (kk * 16 + a_k) * 2);
        #pragma unroll
        for (int np = 0; np < 2; np++)
            ldsm4(bf[buf][np], bbase + (b_n + np * 16) * RSB + (kk * 16 + b_k) * 2);
    };
    auto do_mma = [&](int buf) {
        #pragma unroll
        for (int mt = 0; mt < 4; mt++)
            #pragma unroll
            for (int nt = 0; nt < 4; nt++)
                mma_bf16(acc[mt][nt], af[buf][mt], &bf[buf][nt >> 1][(nt & 1) * 2]);
    };

    load_stage(0); load_stage(1);

    for (int s = 0; s < NSTEP; s++) {
        if (s + 2 < NSTEP) {
            asm volatile("cp.async.wait_group 1;" ::: "memory");
            __syncthreads();
            load_stage(s + 2);
        } else if (s + 1 < NSTEP) {
            asm volatile("cp.async.wait_group 1;" ::: "memory");
            __syncthreads();
        } else {
            asm volatile("cp.async.wait_group 0;" ::: "memory");
            __syncthreads();
        }

        uint32_t abase = sb + (s % 3) * STAGE_B;
        uint32_t bbase = abase + A_BYTES;

        load_frags(abase, bbase, 0, 0);
        #pragma unroll
        for (int kk = 0; kk < 4; kk++) {
            if (kk < 3) load_frags(abase, bbase, kk + 1, (kk + 1) & 1);
            do_mma(kk & 1);
        }
    }

    int crow0 = m0 + wm + (lane >> 2);
    int ccol0 = n0 + wn + (lane & 3) * 2;
    #pragma unroll
    for (int mt = 0; mt < 4; mt++) {
        #pragma unroll
        for (int half = 0; half < 2; half++) {
            int row = crow0 + mt * 16 + half * 8;
            #pragma unroll
            for (int nt = 0; nt < 4; nt++) {
                int col = ccol0 + nt * 8;
                float f0 = acc[mt][nt][half * 2]     + bp[col];
                float f1 = acc[mt][nt][half * 2 + 1] + bp[col + 1];
                if (MODE == 0) {
                    if (lgt) {
                        float2 o; o.x = f0; o.y = f1;
                        *(float2*)(g_logits + (size_t)row * NCAT + col) = o;
                    } else {
                        uint32_t pk;
                        asm("cvt.rn.bf16x2.f32 %0, %1, %2;" : "=r"(pk) : "f"(f1), "f"(f0));
                        *(uint32_t*)((__nv_bfloat16*)Cout + (size_t)row * ldcc + col) = pk;
                    }
                } else {
                    const float* qr = resid + (size_t)row * ldcc + col;
                    float2 o;
                    o.x = qr[0] + gamma[col]     * f0;
                    o.y = qr[1] + gamma[col + 1] * f1;
                    *(float2*)((float*)Cout + (size_t)row * ldcc + col) = o;
                }
            }
        }
    }
}

// ------- prep: softmax + per-point corner weights/indices (warp per query) --------
__global__ __launch_bounds__(256) void prep_kernel(const float* __restrict__ refp)
{
    int warp = threadIdx.x >> 5, lane = threadIdx.x & 31;
    int qi = blockIdx.x * 8 + warp;

    const float* lg = g_logits + (size_t)qi * NCAT;
    float x = (lane < 24) ? lg[48 + lane] : -1e30f;
    float m = x;
    #pragma unroll
    for (int o = 16; o; o >>= 1) m = fmaxf(m, __shfl_xor_sync(0xffffffffu, m, o));
    float e = (lane < 24) ? __expf(x - m) : 0.f;
    float ss = e;
    #pragma unroll
    for (int o = 16; o; o >>= 1) ss += __shfl_xor_sync(0xffffffffu, ss, o);
    if (lane >= 24) return;
    float aw = e / ss;

    float rx = refp[(size_t)qi * 2 + 0] * (float)HW_ - 0.5f;
    float ry = refp[(size_t)qi * 2 + 1] * (float)HW_ - 0.5f;
    // offsets for point j=lane are at lg[2j], lg[2j+1]
    float xf = rx + lg[lane * 2];
    float yf = ry + lg[lane * 2 + 1];
    float x0f = floorf(xf), y0f = floorf(yf);
    float wx = xf - x0f, wy = yf - y0f;
    int x0 = (int)x0f, y0 = (int)y0f;
    // validity folded into weights
    float wxl = ((unsigned)x0 < HW_)       ? (1.f - wx) : 0.f;
    float wxr = ((unsigned)(x0 + 1) < HW_) ? wx         : 0.f;
    float wyt = ((unsigned)y0 < HW_)       ? (1.f - wy) : 0.f;
    float wyb = ((unsigned)(y0 + 1) < HW_) ? wy         : 0.f;
    int xc0 = min(max(x0, 0), HW_ - 1);
    int xc1 = min(max(x0 + 1, 0), HW_ - 1);
    int yc0 = min(max(y0, 0), HW_ - 1);
    int yc1 = min(max(y0 + 1, 0), HW_ - 1);
    float4 w;
    w.x = aw * wyt * wxl;
    w.y = aw * wyt * wxr;
    w.z = aw * wyb * wxl;
    w.w = aw * wyb * wxr;
    uint2 pos;
    pos.x = (uint32_t)(yc0 * HW_ + xc0) | ((uint32_t)(yc0 * HW_ + xc1) << 16);
    pos.y = (uint32_t)(yc1 * HW_ + xc0) | ((uint32_t)(yc1 * HW_ + xc1) << 16);
    g_wdesc[qi * 24 + lane] = w;
    g_pdesc[qi * 24 + lane] = pos;
}

// ------- lean sampler: descriptor-driven, warp per (query, head) ------------------
__global__ __launch_bounds__(256) void sample_kernel()
{
    int w = blockIdx.x * 8 + (threadIdx.x >> 5);
    int lane = threadIdx.x & 31;
    int h  = w % HEADS_;
    int qi = w / HEADS_;
    int b  = qi >> 12;

    float a0 = 0.f, a1 = 0.f, a2 = 0.f, a3 = 0.f;
    const uint2* vp = (const uint2*)(g_valb + (size_t)b * NQ_ * DIM_ + h * HD_) + lane;
    const int POS = DIM_ / 4;   // uint2 per spatial position = 192

    #pragma unroll
    for (int p = 0; p < POINTS_; p++) {
        float4 wt = g_wdesc[qi * 24 + h * POINTS_ + p];   // broadcast loads
        uint2 pos = g_pdesc[qi * 24 + h * POINTS_ + p];
        int i00 = pos.x & 0xFFFF, i01 = pos.x >> 16;
        int i10 = pos.y & 0xFFFF, i11 = pos.y >> 16;
        uint2 q00 = vp[i00 * POS];
        uint2 q01 = vp[i01 * POS];
        uint2 q10 = vp[i10 * POS];
        uint2 q11 = vp[i11 * POS];
        float2 f;
        f = __bfloat1622float2(*(__nv_bfloat162*)&q00.x);
        a0 = fmaf(wt.x, f.x, a0); a1 = fmaf(wt.x, f.y, a1);
        f = __bfloat1622float2(*(__nv_bfloat162*)&q00.y);
        a2 = fmaf(wt.x, f.x, a2); a3 = fmaf(wt.x, f.y, a3);
        f = __bfloat1622float2(*(__nv_bfloat162*)&q01.x);
        a0 = fmaf(wt.y, f.x, a0); a1 = fmaf(wt.y, f.y, a1);
        f = __bfloat1622float2(*(__nv_bfloat162*)&q01.y);
        a2 = fmaf(wt.y, f.x, a2); a3 = fmaf(wt.y, f.y, a3);
        f = __bfloat1622float2(*(__nv_bfloat162*)&q10.x);
        a0 = fmaf(wt.z, f.x, a0); a1 = fmaf(wt.z, f.y, a1);
        f = __bfloat1622float2(*(__nv_bfloat162*)&q10.y);
        a2 = fmaf(wt.z, f.x, a2); a3 = fmaf(wt.z, f.y, a3);
        f = __bfloat1622float2(*(__nv_bfloat162*)&q11.x);
        a0 = fmaf(wt.w, f.x, a0); a1 = fmaf(wt.w, f.y, a1);
        f = __bfloat1622float2(*(__nv_bfloat162*)&q11.y);
        a2 = fmaf(wt.w, f.x, a2); a3 = fmaf(wt.w, f.y, a3);
    }
    uint2 pk;
    asm("cvt.rn.bf16x2.f32 %0, %1, %2;" : "=r"(pk.x) : "f"(a1), "f"(a0));
    asm("cvt.rn.bf16x2.f32 %0, %1, %2;" : "=r"(pk.y) : "f"(a3), "f"(a2));
    ((uint2*)(g_attnb + (size_t)qi * DIM_ + h * HD_))[lane] = pk;
}

// ---------------- launch ----------------
extern "C" void kernel_launch(void* const* d_in, const int* in_sizes, int n_in,
                              void* d_out, int out_size)
{
    const float* query = (const float*)d_in[0];
    const float* refp  = (const float*)d_in[1];
    const float* feat  = (const float*)d_in[2];
    const float* lnw   = (const float*)d_in[5];
    const float* lnb   = (const float*)d_in[6];
    const float* vpw   = (const float*)d_in[7];
    const float* vpb   = (const float*)d_in[8];
    const float* offw  = (const float*)d_in[9];
    const float* offb  = (const float*)d_in[10];
    const float* aww   = (const float*)d_in[11];
    const float* awb   = (const float*)d_in[12];
    const float* outw  = (const float*)d_in[13];
    const float* outb  = (const float*)d_in[14];
    const float* gamma = (const float*)d_in[15];
    float* out = (float*)d_out;

    __nv_bfloat16 *p_featb, *p_valb, *p_attnb, *p_vpwt, *p_outwt;
    cudaGetSymbolAddress((void**)&p_featb, g_featb);
    cudaGetSymbolAddress((void**)&p_valb,  g_valb);
    cudaGetSymbolAddress((void**)&p_attnb, g_attnb);
    cudaGetSymbolAddress((void**)&p_vpwt,  g_vpwt);
    cudaGetSymbolAddress((void**)&p_outwt, g_outwt);

    const int SMEM = 3 * STAGE_B;   // 82944
    cudaFuncSetAttribute(gemm_bf16<0>, cudaFuncAttributeMaxDynamicSharedMemorySize, SMEM);
    cudaFuncSetAttribute(gemm_bf16<1>, cudaFuncAttributeMaxDynamicSharedMemorySize, SMEM);

    dim3 g0(NVT + 2, NROWS_ / 128);   // (14, 64): 12 value tiles + 2 logits tiles
    dim3 g1(NVT, NROWS_ / 128);       // (12, 64)

    prologue_kernel<<<PB_TOT, 384>>>(query, lnw, lnb, feat, vpw, outw,
                                     offw, offb, aww, awb);
    gemm_bf16<0><<<g0, 128, SMEM>>>(p_featb, p_vpwt, vpb, p_valb, DIM_, nullptr, nullptr);
    prep_kernel<<<NROWS_ / 8, 256>>>(refp);
    sample_kernel<<<NROWS_ * HEADS_ / 8, 256>>>();
    gemm_bf16<1><<<g1, 128, SMEM>>>(p_attnb, p_outwt, outb, out, DIM_, query, gamma);
}